// round 15
// baseline (speedup 1.0000x reference)
#include <cuda_runtime.h>

#define NM       32
#define NIN      24
#define NSTEPS   199            // EVAL_PTS - 1
#define NB       2048           // fixed batch
#define WPB      7              // warps per block; ONE row per warp
#define ITHREADS (WPB * 32)     // 224
#define IGRID    ((NB + WPB - 1) / WPB)   // 293; 2 blocks/SM resident -> ~one wave
#define PTHREADS 512            // prelude block
#define DUPK     24             // k's with duplicated T2; rest packed+swap

typedef unsigned long long u64;

__device__ float2 g_T2[NM * NM];   // T2 row-major [mode j][k]

static __device__ __forceinline__ float rg(const float* p, int i, int cap) {
    return (i < cap) ? p[i] : 0.0f;
}
static __device__ __forceinline__ u64 fma2(u64 a, u64 b, u64 c) {
    u64 d;
    asm("fma.rn.f32x2 %0, %1, %2, %3;" : "=l"(d) : "l"(a), "l"(b), "l"(c));
    return d;
}
static __device__ __forceinline__ u64 packf2(float x, float y) {
    u64 p;
    asm("mov.b64 %0, {%1, %2};" : "=l"(p) : "f"(x), "f"(y));
    return p;
}
static __device__ __forceinline__ float lo32(u64 v) { return __uint_as_float((unsigned)v); }
static __device__ __forceinline__ float hi32(u64 v) { return __uint_as_float((unsigned)(v >> 32)); }
static __device__ __forceinline__ u64 swap2(u64 v) { return packf2(hi32(v), lo32(v)); }

// ---------------------------------------------------------------------
// Prelude matmul slice (512-thread layout): thread owns row r, cols c2,c2+1.
// ---------------------------------------------------------------------
template <bool TRANSA>
static __device__ __forceinline__ void mm2(float2 acc[2],
                                           const float2* __restrict__ A,
                                           const float2* __restrict__ B,
                                           int r, int c2) {
    const ulonglong2* __restrict__ B2 = (const ulonglong2*)B;
    u64 E0 = 0, F0 = 0, E1 = 0, F1 = 0;
    #pragma unroll 8
    for (int k = 0; k < 32; k++) {
        const float2 a = TRANSA ? A[k * 32 + r] : A[r * 32 + k];
        u64 au  = packf2(a.x, a.y);
        u64 asw = packf2(a.y, a.x);
        ulonglong2 bb = B2[k * 16 + (c2 >> 1)];
        E0 = fma2(au,  bb.x, E0);
        F0 = fma2(asw, bb.x, F0);
        E1 = fma2(au,  bb.y, E1);
        F1 = fma2(asw, bb.y, F1);
    }
    acc[0] = make_float2(lo32(E0) - hi32(E0), lo32(F0) + hi32(F0));
    acc[1] = make_float2(lo32(E1) - hi32(E1), lo32(F1) + hi32(F1));
}

// =====================================================================
// Prelude (1 block, 512 threads):
//   X = i*H; s from min(inf-norm, 1.45*power-iter estimate), th0=0.9;
//   U = (Taylor12(X/2^s))^(2^s); V = U^T U;
//   S = sum_{n=0}^{255} (V/1.1)^n via doubling; mix = (V S)/1.1;
//   g_T2 = -(kappa kappa^T) o (0.5 I + mix).
// =====================================================================
__global__ void __launch_bounds__(PTHREADS, 1)
prelude_kernel(const float* __restrict__ kappa, const float* __restrict__ params,
               int ka_cap, int par_cap)
{
    __shared__ __align__(16) float2 M0[1024], M1[1024], M2[1024], M3[1024];
    __shared__ int sh_s;

    const unsigned FULL = 0xffffffffu;
    const int tid = threadIdx.x;
    const int mr  = tid >> 4;          // row 0..31
    const int mc2 = (tid & 15) * 2;    // col base 0,2,..30

    // ---- X = i*H (unscaled) -> M0 ----
    #pragma unroll
    for (int j = 0; j < 2; j++) {
        int c = mc2 + j, r = mr;
        float hr, hi;
        if (r < c) {
            int idx = r * 31 - (r * (r - 1)) / 2 + (c - r - 1);
            hr = rg(params, idx, par_cap);
            hi = rg(params, 496 + idx, par_cap);
        } else if (r > c) {
            int idx = c * 31 - (c * (c - 1)) / 2 + (r - c - 1);
            hr =  rg(params, idx, par_cap);
            hi = -rg(params, 496 + idx, par_cap);
        } else if (r < 31) {
            hr = rg(params, 992 + r, par_cap);
            hi = 0.0f;
        } else {
            float sd = 0.0f;
            for (int t = 0; t < 31; t++) sd += rg(params, 992 + t, par_cap);
            hr = -sd;
            hi = 0.0f;
        }
        M0[r * 32 + c] = make_float2(-hi, hr);
    }
    __syncthreads();

    // ---- norm estimate on warp 0 ----
    if (tid < 32) {
        float v = 0.0f;
        for (int k = 0; k < 32; k++) {
            float2 a = M0[tid * 32 + k];
            v += fabsf(a.x) + fabsf(a.y);
        }
        float mx = v;
        #pragma unroll
        for (int o = 16; o; o >>= 1) mx = fmaxf(mx, __shfl_xor_sync(FULL, mx, o));

        float2 x = make_float2(1.0f, 0.07f * (float)tid - 1.0f);
        float est = 1.0f;
        for (int it = 0; it < 10; it++) {
            float yr = 0.0f, yi = 0.0f;
            #pragma unroll
            for (int k = 0; k < 32; k++) {
                float xr = __shfl_sync(FULL, x.x, k);
                float xi = __shfl_sync(FULL, x.y, k);
                float2 a = M0[tid * 32 + k];
                yr = fmaf(a.x, xr, fmaf(-a.y, xi, yr));
                yi = fmaf(a.x, xi, fmaf( a.y, xr, yi));
            }
            float nn = fmaf(yr, yr, yi * yi);
            #pragma unroll
            for (int o = 16; o; o >>= 1) nn += __shfl_xor_sync(FULL, nn, o);
            float nrm = sqrtf(fmaxf(nn, 1e-30f));
            est = nrm;
            float inv = 1.0f / nrm;
            x.x = yr * inv; x.y = yi * inv;
        }
        if (tid == 0) {
            float use = fminf(mx, 1.45f * est);
            int s = 0; float th = 0.9f;
            while (use > th && s < 15) { th *= 2.0f; s++; }
            sh_s = s;
        }
    }
    __syncthreads();
    const int s = sh_s;
    {
        float sc = ldexpf(1.0f, -s);
        #pragma unroll
        for (int j = 0; j < 2; j++) {
            int e = mr * 32 + mc2 + j;
            float2 xv = M0[e];
            M0[e] = make_float2(xv.x * sc, xv.y * sc);
        }
    }

    // ---- E = I ----
    #pragma unroll
    for (int j = 0; j < 2; j++) {
        int e = mr * 32 + mc2 + j;
        M1[e] = make_float2((mr == mc2 + j) ? 1.0f : 0.0f, 0.0f);
    }
    __syncthreads();

    // ---- Horner: E = I + (X*E)/n, n = 12..1 ----
    float2* E = M1;
    float2* T = M2;
    for (int n = 12; n >= 1; n--) {
        float inv = 1.0f / (float)n;
        float2 acc[2];
        mm2<false>(acc, M0, E, mr, mc2);
        #pragma unroll
        for (int j = 0; j < 2; j++) {
            float d = (mr == mc2 + j) ? 1.0f : 0.0f;
            T[mr * 32 + mc2 + j] = make_float2(d + acc[j].x * inv, acc[j].y * inv);
        }
        __syncthreads();
        float2* tmp = E; E = T; T = tmp;
    }

    // ---- s squarings ----
    for (int q = 0; q < s; q++) {
        float2 acc[2];
        mm2<false>(acc, E, E, mr, mc2);
        #pragma unroll
        for (int j = 0; j < 2; j++) T[mr * 32 + mc2 + j] = acc[j];
        __syncthreads();
        float2* tmp = E; E = T; T = tmp;
    }

    // ---- V = U^T U -> M0 ----
    {
        float2 acc[2];
        mm2<true>(acc, E, E, mr, mc2);
        __syncthreads();
        #pragma unroll
        for (int j = 0; j < 2; j++) M0[mr * 32 + mc2 + j] = acc[j];
    }
    __syncthreads();

    // ---- Neumann via doubling: A = V/1.1; S = I + A; B = A ----
    float2* pS = E;
    float2* pB = T;
    float2* pT = M3;
    {
        const float ia = 1.0f / 1.1f;
        #pragma unroll
        for (int j = 0; j < 2; j++) {
            int e = mr * 32 + mc2 + j;
            float2 v = M0[e];
            float2 a = make_float2(v.x * ia, v.y * ia);
            float d = (mr == mc2 + j) ? 1.0f : 0.0f;
            pB[e] = a;
            pS[e] = make_float2(d + a.x, a.y);
        }
    }
    __syncthreads();

    for (int it = 0; it < 7; it++) {
        {
            float2 acc[2];
            mm2<false>(acc, pB, pB, mr, mc2);
            #pragma unroll
            for (int j = 0; j < 2; j++) pT[mr * 32 + mc2 + j] = acc[j];
        }
        __syncthreads();
        { float2* t = pB; pB = pT; pT = t; }
        {
            float2 acc[2];
            mm2<false>(acc, pS, pB, mr, mc2);
            #pragma unroll
            for (int j = 0; j < 2; j++) pT[mr * 32 + mc2 + j] = acc[j];
        }
        __syncthreads();
        #pragma unroll
        for (int j = 0; j < 2; j++) {
            int e = mr * 32 + mc2 + j;
            float2 sv = pS[e], tv = pT[e];
            pS[e] = make_float2(sv.x + tv.x, sv.y + tv.y);
        }
        __syncthreads();
    }

    // ---- mix = (V*S)/1.1 ; g_T2 = -(k k^T) o (0.5I + mix) ----
    {
        float2 acc[2];
        mm2<false>(acc, M0, pS, mr, mc2);
        const float ia = 1.0f / 1.1f;
        #pragma unroll
        for (int j = 0; j < 2; j++) {
            int r = mr, c = mc2 + j;
            float tr = fmaf(acc[j].x, ia, (r == c) ? 0.5f : 0.0f);
            float ti = acc[j].y * ia;
            float coef = -rg(kappa, r, ka_cap) * rg(kappa, c, ka_cap);
            g_T2[r * 32 + c] = make_float2(coef * tr, coef * ti);
        }
    }
}

// =====================================================================
// Integrator: ONE row per warp, lane j = mode j. 2 blocks/SM resident
// (launch_bounds 224,2 -> <=144 regs). T2: k<24 duplicated in regs
// ({tr,tr},{ti,ti}), k>=24 packed {tr,ti} + V-swap. LDS.128 loads two
// k's per instruction. Split accumulators keep chains <= 12 fma2 deep.
// =====================================================================
static __device__ __forceinline__ float2 f_eval(float2 V,
                                                const u64* __restrict__ crr,
                                                const u64* __restrict__ cii,
                                                const u64* __restrict__ bq,
                                                float2* __restrict__ shv,
                                                int lane, float wj, float nl2) {
    shv[lane] = V;
    __syncwarp();
    const ulonglong2* __restrict__ q2 = (const ulonglong2*)shv;
    u64 Aa0 = 0, Aa1 = 0, Ab0 = 0, Ab1 = 0, Ae = 0, Af = 0;
    #pragma unroll
    for (int kk = 0; kk < DUPK / 2; kk++) {           // k = 2kk, 2kk+1
        ulonglong2 Wp = q2[kk];
        Aa0 = fma2(Wp.x, crr[2 * kk],     Aa0);
        Ab0 = fma2(Wp.x, cii[2 * kk],     Ab0);
        Aa1 = fma2(Wp.y, crr[2 * kk + 1], Aa1);
        Ab1 = fma2(Wp.y, cii[2 * kk + 1], Ab1);
    }
    #pragma unroll
    for (int kk = DUPK / 2; kk < NM / 2; kk++) {      // packed tail
        ulonglong2 Wp = q2[kk];
        int b = 2 * kk - DUPK;
        Ae = fma2(Wp.x,        bq[b],     Ae);
        Af = fma2(swap2(Wp.x), bq[b],     Af);
        Ae = fma2(Wp.y,        bq[b + 1], Ae);
        Af = fma2(swap2(Wp.y), bq[b + 1], Af);
    }
    float pr = ((lo32(Aa0) + lo32(Aa1)) - (hi32(Ab0) + hi32(Ab1)))
             + (lo32(Ae) - hi32(Ae));
    float pi = ((hi32(Aa0) + hi32(Aa1)) + (lo32(Ab0) + lo32(Ab1)))
             + (lo32(Af) + hi32(Af));
    float w = fmaf(nl2, fmaf(V.x, V.x, V.y * V.y), wj);
    return make_float2(fmaf(-w, V.y, pr), fmaf(w, V.x, pi));
}

__global__ void __launch_bounds__(ITHREADS, 2)
integrate_kernel(const float* __restrict__ A0r, const float* __restrict__ A0i,
                 const float* __restrict__ omega, const float* __restrict__ nl,
                 float* __restrict__ out,
                 int a0r_cap, int a0i_cap, int om_cap, int nl_cap,
                 long long cap_f, int pair_mode)
{
    __shared__ __align__(16) float2 shV[WPB][2][NM];   // 3.5 KB

    const int warp = threadIdx.x >> 5;
    const int lane = threadIdx.x & 31;
    const int row  = blockIdx.x * WPB + warp;
    if (row >= NB) return;

    // T2 row for this lane: 24 duplicated + 8 packed
    u64 crr[DUPK], cii[DUPK], bq[NM - DUPK];
    #pragma unroll
    for (int k = 0; k < DUPK; k++) {
        float2 t = g_T2[lane * NM + k];
        crr[k] = packf2(t.x, t.x);
        cii[k] = packf2(t.y, t.y);
    }
    {
        const u64* t2q = (const u64*)g_T2;
        #pragma unroll
        for (int k = 0; k < NM - DUPK; k++) bq[k] = t2q[lane * NM + DUPK + k];
    }

    const float wj  = rg(omega, lane, om_cap);
    const float nv  = rg(nl, 0, nl_cap);
    const float nl2 = nv * nv;

    float2 A;
    if (lane < NIN) {
        A.x = rg(A0r, row * NIN + lane, a0r_cap);
        A.y = rg(A0i, row * NIN + lane, a0i_cap);
    } else {
        A.x = 1.0f; A.y = 0.0f;
    }

    const long long stride_c = (long long)NB * NM;
    long long cidx = (long long)row * NM + lane;

    if (pair_mode) {
        long long o = 2 * cidx;
        if (o + 1 < cap_f) { out[o] = A.x; out[o + 1] = A.y; }
    } else {
        if (cidx < cap_f) out[cidx] = A.x;
    }

    const double dtd = 1.0 / (double)NSTEPS;
    const float dtf = (float)dtd;
    const float hdt = (float)(0.5 * dtd);
    const float dt6 = (float)(dtd / 6.0);

    float2* sh0 = &shV[warp][0][0];
    float2* sh1 = &shV[warp][1][0];

    for (int step = 0; step < NSTEPS; step++) {
        float2 k1 = f_eval(A, crr, cii, bq, sh0, lane, wj, nl2);
        float2 st = make_float2(fmaf(hdt, k1.x, A.x), fmaf(hdt, k1.y, A.y));
        float2 k2 = f_eval(st, crr, cii, bq, sh1, lane, wj, nl2);
        st = make_float2(fmaf(hdt, k2.x, A.x), fmaf(hdt, k2.y, A.y));
        float2 k3 = f_eval(st, crr, cii, bq, sh0, lane, wj, nl2);
        st = make_float2(fmaf(dtf, k3.x, A.x), fmaf(dtf, k3.y, A.y));
        float2 k4 = f_eval(st, crr, cii, bq, sh1, lane, wj, nl2);

        float sx = k1.x + 2.0f * (k2.x + k3.x) + k4.x;
        float sy = k1.y + 2.0f * (k2.y + k3.y) + k4.y;
        A.x = fmaf(dt6, sx, A.x);
        A.y = fmaf(dt6, sy, A.y);

        cidx += stride_c;
        if (pair_mode) {
            long long o = 2 * cidx;
            if (o + 1 < cap_f) { out[o] = A.x; out[o + 1] = A.y; }
        } else {
            if (cidx < cap_f) out[cidx] = A.x;
        }
    }
}

extern "C" void kernel_launch(void* const* d_in, const int* in_sizes, int n_in,
                              void* d_out, int out_size)
{
    // Positional binding per documented metadata order:
    //   A0_real, A0_imag, omega, kappa, nonlinearity, params
    const long long want[6] = {NB * NIN, NB * NIN, NM, NM, 1, NM * NM - 1};
    const float* P[6];
    int cap[6];
    for (int j = 0; j < 6; j++) {
        if (j < n_in) {
            P[j] = (const float*)d_in[j];
            long long s = in_sizes[j];
            cap[j] = (int)(s < want[j] ? s : want[j]);
        } else {
            P[j] = (const float*)d_out;   // never dereferenced (cap 0)
            cap[j] = 0;
        }
    }

    // Output interpretation — identical to the passing round 10/12/13/14 logic.
    const long long PAIRS_F = 26214400LL;   // 2 * 200*2048*32
    long long cap_f = (long long)out_size;
    int pair_mode = (cap_f >= PAIRS_F) ? 1 : 0;
    if (cap_f > PAIRS_F) cap_f = PAIRS_F;

    prelude_kernel<<<1, PTHREADS>>>(P[3], P[5], cap[3], cap[5]);
    integrate_kernel<<<IGRID, ITHREADS>>>(P[0], P[1], P[2], P[4],
                                          (float*)d_out,
                                          cap[0], cap[1], cap[2], cap[4],
                                          cap_f, pair_mode);
}